// round 7
// baseline (speedup 1.0000x reference)
#include <cuda_runtime.h>
#include <math.h>

#define DI __device__ __forceinline__

// ---------- static scratch ----------
__device__ float g_feats[262144];          // [2048][128]
__device__ float g_Q[524288];              // [2048][256]
__device__ float g_adj[2097152];           // [2][1024][1024]
__device__ float g_egi[6144], g_egj[6144]; // [3][2048]
__device__ int   g_cnt[6144];
__device__ int   g_eidx[6291456];          // [3][2048][1024] worst case
__device__ float g_ew[6291456];
__device__ float g_froot[786432], g_fnbr[786432];
__device__ float g_cout[786432], g_h[786432], g_ys[786432];
__device__ float g_mu[384], g_var[384];
__device__ int   g_pmaxI[768];
__device__ float g_pools[768], g_coef[768];
__device__ float g_fused[262144], g_yfin[262144];

DI float sigm(float z) { return 1.f / (1.f + __expf(-z)); }

__global__ void k_zero() { int i = blockIdx.x*256+threadIdx.x; if (i < 768) g_pmaxI[i] = 0; }

// ---------- projection: x -> Q + feats. grid 128 (b*64+blk), 256 thr, 165632B dyn smem ----------
__global__ void __launch_bounds__(256) k_proj(const float* __restrict__ x,
    const float* __restrict__ anchor, const float* __restrict__ sigma_raw) {
  extern __shared__ float sm[];
  float*  pix = sm;                    // 128*257
  float2* anc = (float2*)(sm + 32896); // 2048 x (inv, a*inv)
  float*  sa  = sm + 36992;            // 16*257
  float*  red = sm + 41104;            // 16*17
  float*  Ssm = sm + 41376;
  float*  Isn = sm + 41392;
  int t = threadIdx.x, b = blockIdx.x >> 6, blk = blockIdx.x & 63;
  int by = blk >> 3, bx = blk & 7;
  for (int i = t; i < 2048; i += 256) {
    int node = blk*16 + (i >> 7), c = i & 127;
    float a = anchor[node*128 + c];
    float inv = 1.f + __expf(-sigma_raw[node*128 + c]);   // 1/sigmoid
    anc[i] = make_float2(inv, a*inv);
  }
  int p = t, hb = p >> 4, wb = p & 15;
  const float* xb = x + (size_t)b*2097152 + (size_t)(by*16+hb)*128 + bx*16 + wb;
  for (int c = 0; c < 128; ++c) pix[c*257 + p] = xb[(size_t)c*16384];
  __syncthreads();
  float acc[16];
  #pragma unroll
  for (int k = 0; k < 16; ++k) acc[k] = 0.f;
  for (int c = 0; c < 128; ++c) {
    float pv = pix[c*257 + p];
    #pragma unroll
    for (int k = 0; k < 16; ++k) {
      float2 q = anc[k*128 + c];
      float d = fmaf(pv, q.x, -q.y);
      acc[k] = fmaf(d, d, acc[k]);
    }
  }
  float mx = -3.4e38f;
  #pragma unroll
  for (int k = 0; k < 16; ++k) { acc[k] *= -0.5f; mx = fmaxf(mx, acc[k]); }
  float ss = 0.f;
  #pragma unroll
  for (int k = 0; k < 16; ++k) { acc[k] = __expf(acc[k]-mx); ss += acc[k]; }
  float is = 1.f/ss;
  #pragma unroll
  for (int k = 0; k < 16; ++k) {
    float v = acc[k]*is;
    sa[k*257 + p] = v;
    g_Q[(size_t)(b*1024 + blk*16 + k)*256 + p] = v;
  }
  __syncthreads();
  int k = t >> 4, u = t & 15;
  { float sp = 0.f;
    for (int q = 0; q < 16; ++q) sp += sa[k*257 + u + 16*q];
    red[k*17 + u] = sp; }
  __syncthreads();
  if (t < 16) { float s2 = 0.f; for (int u2 = 0; u2 < 16; ++u2) s2 += red[t*17+u2]; Ssm[t] = s2; }
  __syncthreads();
  float am[8];
  #pragma unroll
  for (int j = 0; j < 8; ++j) am[j] = 0.f;
  for (int pp = 0; pp < 256; ++pp) {
    float sv = sa[k*257 + pp];
    #pragma unroll
    for (int j = 0; j < 8; ++j) am[j] = fmaf(sv, pix[(u+16*j)*257 + pp], am[j]);
  }
  float Sv = Ssm[k], val[8], nn = 0.f;
  #pragma unroll
  for (int j = 0; j < 8; ++j) {
    float2 q = anc[k*128 + u + 16*j];
    float v = fmaf(am[j], q.x, -q.y*Sv);       // (am - a*S)*inv
    val[j] = v; nn = fmaf(v, v, nn);
  }
  red[k*17 + u] = nn;
  __syncthreads();
  if (t < 16) { float s2 = 0.f; for (int u2 = 0; u2 < 16; ++u2) s2 += red[t*17+u2];
    Isn[t] = rsqrtf(fmaxf(s2, 1e-24f)); }
  __syncthreads();
  float iv = Isn[k];
  #pragma unroll
  for (int j = 0; j < 8; ++j)
    g_feats[(size_t)(b*1024 + blk*16 + k)*128 + u + 16*j] = val[j]*iv;
}

// ---------- Gram: adj = F F^T. grid (16,16,2), 256 thr ----------
__global__ void __launch_bounds__(256) k_gram() {
  __shared__ float As[64*33], Bs[64*33];
  int b = blockIdx.z, i0 = blockIdx.x*64, j0 = blockIdx.y*64;
  int t = threadIdx.x, tx = t & 15, ty = t >> 4;
  float acc[4][4];
  #pragma unroll
  for (int i = 0; i < 4; ++i)
    #pragma unroll
    for (int j = 0; j < 4; ++j) acc[i][j] = 0.f;
  const float* FA = g_feats + (size_t)b*131072 + (size_t)i0*128;
  const float* FB = g_feats + (size_t)b*131072 + (size_t)j0*128;
  for (int kc = 0; kc < 4; ++kc) {
    #pragma unroll
    for (int q = 0; q < 8; ++q) { int fi = t + 256*q, r = fi >> 5, kk = fi & 31;
      As[r*33+kk] = FA[r*128 + kc*32 + kk];
      Bs[r*33+kk] = FB[r*128 + kc*32 + kk]; }
    __syncthreads();
    for (int kk = 0; kk < 32; ++kk) {
      float av[4], bv[4];
      #pragma unroll
      for (int i = 0; i < 4; ++i) av[i] = As[(ty*4+i)*33 + kk];
      #pragma unroll
      for (int j = 0; j < 4; ++j) bv[j] = Bs[(tx*4+j)*33 + kk];
      #pragma unroll
      for (int i = 0; i < 4; ++i)
        #pragma unroll
        for (int j = 0; j < 4; ++j) acc[i][j] = fmaf(av[i], bv[j], acc[i][j]);
    }
    __syncthreads();
  }
  #pragma unroll
  for (int i = 0; i < 4; ++i) {
    float4 o = make_float4(acc[i][0], acc[i][1], acc[i][2], acc[i][3]);
    *(float4*)&g_adj[(size_t)b*1048576 + (size_t)(i0+ty*4+i)*1024 + j0 + tx*4] = o;
  }
}

// ---------- gates ----------
__global__ void __launch_bounds__(256) k_gates(const float* __restrict__ ws,
    const float* __restrict__ wd, const float* __restrict__ bg) {
  int row = blockIdx.x*8 + (threadIdx.x >> 5), l = threadIdx.x & 31;
  float4 f = *(const float4*)&g_feats[(size_t)row*128 + l*4];
  for (int s = 0; s < 3; ++s) {
    float4 a = *(const float4*)&ws[s*128 + l*4];
    float4 d = *(const float4*)&wd[s*128 + l*4];
    float gi = f.x*a.x + f.y*a.y + f.z*a.z + f.w*a.w;
    float gj = f.x*d.x + f.y*d.y + f.z*d.z + f.w*d.w;
    #pragma unroll
    for (int o = 16; o > 0; o >>= 1) {
      gi += __shfl_xor_sync(0xffffffffu, gi, o);
      gj += __shfl_xor_sync(0xffffffffu, gj, o);
    }
    if (l == 0) { g_egi[s*2048+row] = expf(-(gi + bg[s])); g_egj[s*2048+row] = expf(-gj); }
  }
}

// ---------- edge compaction (warp/row, j-ordered deterministic) ----------
__global__ void __launch_bounds__(256) k_compact() {
  int row = blockIdx.x*8 + (threadIdx.x >> 5), l = threadIdx.x & 31;
  int b = row >> 10, i = row & 1023, iblk = i >> 4;
  float e0 = g_egi[row], e1 = g_egi[2048+row], e2 = g_egi[4096+row];
  const float* ar = g_adj + (size_t)b*1048576 + (size_t)i*1024;
  int c0 = 0, c1 = 0, c2 = 0;
  size_t base = (size_t)row*1024;
  for (int jb = 0; jb < 1024; jb += 32) {
    int j = jb + l;
    float a = ar[j];
    bool same = ((j >> 4) == iblk);
    bool p0 = same && (a > 0.7f), p1 = (!same) && (a > 0.5f), p2 = (a > 0.3f);
    unsigned m0 = __ballot_sync(0xffffffffu, p0);
    unsigned m1 = __ballot_sync(0xffffffffu, p1);
    unsigned m2 = __ballot_sync(0xffffffffu, p2);
    unsigned lt = (1u << l) - 1u;
    if (p0) { int q = c0 + __popc(m0 & lt);
      g_eidx[base+q] = j; g_ew[base+q] = a / (1.f + e0*g_egj[b*1024+j]); }
    if (p1) { int q = c1 + __popc(m1 & lt);
      g_eidx[2097152+base+q] = j; g_ew[2097152+base+q] = a / (1.f + e1*g_egj[2048+b*1024+j]); }
    if (p2) { int q = c2 + __popc(m2 & lt);
      g_eidx[4194304+base+q] = j; g_ew[4194304+base+q] = a / (1.f + e2*g_egj[4096+b*1024+j]); }
    c0 += __popc(m0); c1 += __popc(m1); c2 += __popc(m2);
  }
  if (l == 0) { g_cnt[row] = c0; g_cnt[2048+row] = c1; g_cnt[4096+row] = c2; }
}

// ---------- shared 64x64-tile mm: O_tile = A[64xK=128] @ W[128x128] cols [col0,col0+64) ----------
DI void mm64(const float* __restrict__ A, const float* __restrict__ W, int col0,
             float acc[4][4], float* As, float* Ws) {
  int t = threadIdx.x, tx = t & 15, ty = t >> 4;
  #pragma unroll
  for (int i = 0; i < 4; ++i)
    #pragma unroll
    for (int j = 0; j < 4; ++j) acc[i][j] = 0.f;
  for (int kc = 0; kc < 4; ++kc) {
    #pragma unroll
    for (int q = 0; q < 8; ++q) { int fi = t + 256*q, r = fi >> 5, kk = fi & 31;
      As[r*33+kk] = A[(size_t)r*128 + kc*32 + kk]; }
    #pragma unroll
    for (int q = 0; q < 4; ++q) { int fi = t + 256*q, r = fi >> 5, n2 = fi & 31;
      *(float2*)&Ws[r*68 + n2*2] = *(const float2*)&W[(size_t)(kc*32+r)*128 + col0 + n2*2]; }
    __syncthreads();
    for (int kk = 0; kk < 32; ++kk) {
      float av[4];
      #pragma unroll
      for (int i = 0; i < 4; ++i) av[i] = As[(ty*4+i)*33 + kk];
      float4 bq = *(const float4*)&Ws[kk*68 + tx*4];
      float bv[4] = {bq.x, bq.y, bq.z, bq.w};
      #pragma unroll
      for (int i = 0; i < 4; ++i)
        #pragma unroll
        for (int j = 0; j < 4; ++j) acc[i][j] = fmaf(av[i], bv[j], acc[i][j]);
    }
    __syncthreads();
  }
}

// ---------- feats @ {W_root,W_nbr}. grid (32,2,6) ----------
__global__ void __launch_bounds__(256) k_mm6(const float* __restrict__ Wr, const float* __restrict__ Wn) {
  __shared__ float As[2112], Ws[2176];
  int z = blockIdx.z;
  const float* W = (z < 3) ? Wr + z*16384 : Wn + (z-3)*16384;
  float* O = (z < 3) ? g_froot + (size_t)z*262144 : g_fnbr + (size_t)(z-3)*262144;
  int rt = blockIdx.x*64, col0 = blockIdx.y*64;
  float acc[4][4];
  mm64(g_feats + (size_t)rt*128, W, col0, acc, As, Ws);
  int tx = threadIdx.x & 15, ty = threadIdx.x >> 4;
  #pragma unroll
  for (int i = 0; i < 4; ++i)
    *(float4*)&O[(size_t)(rt+ty*4+i)*128 + col0 + tx*4] =
      make_float4(acc[i][0], acc[i][1], acc[i][2], acc[i][3]);
}

// ---------- sparse aggregation + root ----------
__global__ void __launch_bounds__(128) k_agg() {
  int s = blockIdx.x >> 11, row = blockIdx.x & 2047, c = threadIdx.x, b = row >> 10;
  float v = g_froot[(size_t)s*262144 + (size_t)row*128 + c];
  int cnt = g_cnt[s*2048 + row];
  const int*   ix = g_eidx + (size_t)s*2097152 + (size_t)row*1024;
  const float* wv = g_ew   + (size_t)s*2097152 + (size_t)row*1024;
  const float* FN = g_fnbr + (size_t)s*262144 + (size_t)b*131072;
  for (int e = 0; e < cnt; ++e)
    v = fmaf(wv[e], FN[(size_t)ix[e]*128 + c], v);
  g_cout[(size_t)s*262144 + (size_t)row*128 + c] = v;
}

// ---------- BN stats over 2048 rows ----------
__global__ void __launch_bounds__(512) k_bnstats() {
  __shared__ float ssum[512], ssq[512];
  int s = blockIdx.x, c = threadIdx.x & 127, g = threadIdx.x >> 7;
  float su = 0.f, sq = 0.f;
  for (int r = g; r < 2048; r += 4) {
    float v = g_cout[(size_t)s*262144 + (size_t)r*128 + c];
    su += v; sq = fmaf(v, v, sq);
  }
  ssum[threadIdx.x] = su; ssq[threadIdx.x] = sq;
  __syncthreads();
  if (threadIdx.x < 128) {
    float a = 0.f, b2 = 0.f;
    #pragma unroll
    for (int q = 0; q < 4; ++q) { a += ssum[q*128+c]; b2 += ssq[q*128+c]; }
    float mu = a * (1.f/2048.f);
    g_mu[s*128+c] = mu;
    g_var[s*128+c] = fmaxf(b2*(1.f/2048.f) - mu*mu, 0.f);
  }
}

// ---------- h = bn(cout) + feats ----------
__global__ void __launch_bounds__(256) k_h(const float* __restrict__ gam, const float* __restrict__ bet) {
  int i = blockIdx.x*256 + threadIdx.x;
  int s = i >> 18, c = i & 127, si = s*128 + c, rc = i & 262143;
  float v = g_cout[i];
  g_h[i] = gam[si]*(v - g_mu[si])*rsqrtf(g_var[si] + 1e-5f) + bet[si] + g_feats[rc];
}

// ---------- att + relu + pool max. grid (32,2,3) ----------
__global__ void __launch_bounds__(256) k_att(const float* __restrict__ attW, const float* __restrict__ attb) {
  __shared__ float As[2112], Ws[2176], redm[16*68];
  int s = blockIdx.z, rt = blockIdx.x*64, col0 = blockIdx.y*64, b = rt >> 10;
  float acc[4][4];
  const float* H = g_h + (size_t)s*262144;
  mm64(H + (size_t)rt*128, attW + s*16384, col0, acc, As, Ws);
  int tx = threadIdx.x & 15, ty = threadIdx.x >> 4;
  float cm[4] = {0.f, 0.f, 0.f, 0.f};
  #pragma unroll
  for (int i = 0; i < 4; ++i) {
    int r = rt + ty*4 + i;
    #pragma unroll
    for (int j = 0; j < 4; ++j) {
      int c = col0 + tx*4 + j;
      float hv = H[(size_t)r*128 + c];
      float y = fmaxf(sigm(acc[i][j] + attb[s*128+c]) * hv, 0.f);
      g_ys[(size_t)s*262144 + (size_t)r*128 + c] = y;
      cm[j] = fmaxf(cm[j], y);
    }
  }
  #pragma unroll
  for (int j = 0; j < 4; ++j) redm[ty*68 + tx*4 + j] = cm[j];
  __syncthreads();
  int t = threadIdx.x;
  if (t < 64) {
    float m = 0.f;
    #pragma unroll
    for (int q = 0; q < 16; ++q) m = fmaxf(m, redm[q*68 + t]);
    atomicMax(&g_pmaxI[(s*2+b)*128 + col0 + t], __float_as_int(m));
  }
}

// ---------- pool MLP. grid 6 (e=s*2+b), 128 thr ----------
__global__ void __launch_bounds__(128) k_mlp(const float* __restrict__ W1, const float* __restrict__ b1,
    const float* __restrict__ W2, const float* __restrict__ b2) {
  __shared__ float p[128], h1[128];
  int e = blockIdx.x, s = e >> 1, c = threadIdx.x;
  p[c] = __int_as_float(g_pmaxI[e*128 + c]);
  __syncthreads();
  float a = b1[s*128 + c];
  for (int k = 0; k < 128; ++k) a = fmaf(p[k], W1[s*16384 + k*128 + c], a);
  h1[c] = fmaxf(a, 0.f);
  __syncthreads();
  float o = b2[s*128 + c];
  for (int k = 0; k < 128; ++k) o = fmaf(h1[k], W2[s*16384 + k*128 + c], o);
  g_pools[e*128 + c] = sigm(o);
}

// ---------- scale mixing: a, softmax, coef ----------
__global__ void __launch_bounds__(128) k_mix(const float* __restrict__ lw, const float* __restrict__ lb) {
  __shared__ float part[6][4], aa[6], Ash[6];
  int c = threadIdx.x, w = c >> 5, l = c & 31;
  for (int e = 0; e < 6; ++e) {
    int s = e >> 1;
    float v = g_pools[e*128 + c] * lw[s*128 + c];
    #pragma unroll
    for (int o = 16; o > 0; o >>= 1) v += __shfl_xor_sync(0xffffffffu, v, o);
    if (l == 0) part[e][w] = v;
  }
  __syncthreads();
  if (c < 6) aa[c] = part[c][0] + part[c][1] + part[c][2] + part[c][3] + lb[c >> 1];
  __syncthreads();
  if (c < 2) {
    float a0 = aa[0*2+c], a1 = aa[1*2+c], a2 = aa[2*2+c];
    float m = fmaxf(a0, fmaxf(a1, a2));
    float e0 = __expf(a0-m), e1 = __expf(a1-m), e2 = __expf(a2-m);
    float is = 1.f / (e0+e1+e2);
    Ash[0*2+c] = e0*is; Ash[1*2+c] = e1*is; Ash[2*2+c] = e2*is;
  }
  __syncthreads();
  for (int e = 0; e < 6; ++e) g_coef[e*128 + c] = Ash[e] * g_pools[e*128 + c];
}

// ---------- fused = sum_s coef * ys ----------
__global__ void __launch_bounds__(256) k_fuse() {
  int i = blockIdx.x*256 + threadIdx.x;
  int row = i >> 7, b = row >> 10, c = i & 127;
  float v = 0.f;
  #pragma unroll
  for (int s = 0; s < 3; ++s)
    v = fmaf(g_coef[(s*2+b)*128 + c], g_ys[(size_t)s*262144 + i], v);
  g_fused[i] = v;
}

// ---------- yfin = fused @ lineFu_W + b. grid (32,2) ----------
__global__ void __launch_bounds__(256) k_yfin(const float* __restrict__ W, const float* __restrict__ bias) {
  __shared__ float As[2112], Ws[2176];
  int rt = blockIdx.x*64, col0 = blockIdx.y*64;
  float acc[4][4];
  mm64(g_fused + (size_t)rt*128, W, col0, acc, As, Ws);
  int tx = threadIdx.x & 15, ty = threadIdx.x >> 4;
  #pragma unroll
  for (int i = 0; i < 4; ++i)
    #pragma unroll
    for (int j = 0; j < 4; ++j)
      g_yfin[(size_t)(rt+ty*4+i)*128 + col0 + tx*4 + j] = acc[i][j] + bias[col0 + tx*4 + j];
}

// ---------- reprojection + residual. grid 128, 256 thr ----------
__global__ void __launch_bounds__(256) k_reproj(const float* __restrict__ x, float* __restrict__ out) {
  __shared__ float yf[16*130];
  int b = blockIdx.x >> 6, blk = blockIdx.x & 63, by = blk >> 3, bx = blk & 7;
  int t = threadIdx.x, base = b*1024 + blk*16;
  #pragma unroll
  for (int q = 0; q < 8; ++q) { int fi = t + 256*q, r = fi >> 7, c = fi & 127;
    yf[r*130 + c] = g_yfin[(size_t)(base+r)*128 + c]; }
  float qv[16];
  #pragma unroll
  for (int k = 0; k < 16; ++k) qv[k] = g_Q[(size_t)(base+k)*256 + t];
  __syncthreads();
  int hb = t >> 4, wb = t & 15;
  size_t o0 = (size_t)b*2097152 + (size_t)(by*16+hb)*128 + bx*16 + wb;
  for (int c = 0; c < 128; ++c) {
    float acc = 0.f;
    #pragma unroll
    for (int k = 0; k < 16; ++k) acc = fmaf(yf[k*130 + c], qv[k], acc);
    out[o0 + (size_t)c*16384] = acc + x[o0 + (size_t)c*16384];
  }
}

extern "C" void kernel_launch(void* const* d_in, const int* in_sizes, int n_in,
                              void* d_out, int out_size) {
  const float* x     = (const float*)d_in[0];
  const float* anc   = (const float*)d_in[1];
  const float* sig   = (const float*)d_in[2];
  const float* Wroot = (const float*)d_in[3];
  const float* Wnbr  = (const float*)d_in[4];
  const float* wgs   = (const float*)d_in[5];
  const float* wgd   = (const float*)d_in[6];
  const float* bgate = (const float*)d_in[7];
  const float* gam   = (const float*)d_in[8];
  const float* bet   = (const float*)d_in[9];
  const float* attW  = (const float*)d_in[10];
  const float* attb  = (const float*)d_in[11];
  const float* W1    = (const float*)d_in[12];
  const float* b1    = (const float*)d_in[13];
  const float* W2    = (const float*)d_in[14];
  const float* b2    = (const float*)d_in[15];
  const float* lAw   = (const float*)d_in[16];
  const float* lAb   = (const float*)d_in[17];
  const float* FuW   = (const float*)d_in[18];
  const float* Fub   = (const float*)d_in[19];
  float* out = (float*)d_out;

  cudaFuncSetAttribute(k_proj, cudaFuncAttributeMaxDynamicSharedMemorySize, 165632);

  k_zero<<<3, 256>>>();
  k_proj<<<128, 256, 165632>>>(x, anc, sig);
  k_gram<<<dim3(16,16,2), 256>>>();
  k_gates<<<256, 256>>>(wgs, wgd, bgate);
  k_compact<<<256, 256>>>();
  k_mm6<<<dim3(32,2,6), 256>>>(Wroot, Wnbr);
  k_agg<<<6144, 128>>>();
  k_bnstats<<<3, 512>>>();
  k_h<<<3072, 256>>>(gam, bet);
  k_att<<<dim3(32,2,3), 256>>>(attW, attb);
  k_mlp<<<6, 128>>>(W1, b1, W2, b2);
  k_mix<<<1, 128>>>(lAw, lAb);
  k_fuse<<<1024, 256>>>();
  k_yfin<<<dim3(32,2), 256>>>(FuW, Fub);
  k_reproj<<<128, 256>>>(x, out);
}

// round 9
// speedup vs baseline: 2.1264x; 2.1264x over previous
#include <cuda_runtime.h>
#include <math.h>

#define DI __device__ __forceinline__

// ---------- static scratch ----------
__device__ float g_feats[262144];          // [2048][128]
__device__ float g_Q[524288];              // [2048][256]
__device__ float g_adj[2097152];           // [2][1024][1024]
__device__ float g_egi[6144], g_egj[6144]; // [3][2048]
__device__ float g_froot[786432], g_fnbr[786432];
__device__ float g_cout[786432], g_h[786432], g_ys[786432];
__device__ float g_bnp[12288];             // partial sums [48][128] + sq [48][128]
__device__ float g_mu[384], g_var[384];
__device__ int   g_pmaxI[768];
__device__ float g_pools[768], g_coef[768];
__device__ float g_yfin[262144];

DI float sigm(float z) { return 1.f / (1.f + __expf(-z)); }

// ---------- projection: x -> Q + feats. grid 128 (b*64+blk), 512 thr, 199424B dyn smem ----------
__global__ void __launch_bounds__(512) k_proj(const float* __restrict__ x,
    const float* __restrict__ anchor, const float* __restrict__ sigma_raw) {
  extern __shared__ float sm[];
  float*  pix = sm;                       // 128*257 = 32896
  float2* anc = (float2*)(sm + 32896);    // 2048 x (inv, a*inv)
  float*  sa  = sm + 36992;               // 16*257 = 4112
  float*  amP = sm + 41104;               // 8192 (also logits partials 16*257)
  float*  red = sm + 49296;               // 16*33 = 528
  float*  Ssm = sm + 49824;               // 16
  float*  Isn = sm + 49840;               // 16  (total 49856 floats)
  const int t = threadIdx.x, b = blockIdx.x >> 6, blk = blockIdx.x & 63;
  const int by = blk >> 3, bx = blk & 7;
  for (int i = t; i < 2048; i += 512) {
    int node = blk*16 + (i >> 7), c = i & 127;
    float a = anchor[node*128 + c];
    float inv = 1.f + __expf(-sigma_raw[node*128 + c]);   // 1/sigmoid
    anc[i] = make_float2(inv, a*inv);
  }
  const int p = t & 255, hf = t >> 8;
  {
    const int hb = p >> 4, wb = p & 15;
    const float* xb = x + (size_t)b*2097152 + (size_t)(by*16+hb)*128 + bx*16 + wb;
    for (int cc = 0; cc < 64; ++cc) {
      int c = hf*64 + cc;
      pix[c*257 + p] = xb[(size_t)c*16384];
    }
  }
  __syncthreads();
  // logits: each thread covers 64 channels for its pixel
  float acc[16];
  #pragma unroll
  for (int k = 0; k < 16; ++k) acc[k] = 0.f;
  for (int cc = 0; cc < 64; ++cc) {
    int c = hf*64 + cc;
    float pv = pix[c*257 + p];
    #pragma unroll
    for (int k = 0; k < 16; ++k) {
      float2 q = anc[k*128 + c];
      float d = fmaf(pv, q.x, -q.y);
      acc[k] = fmaf(d, d, acc[k]);
    }
  }
  if (hf == 1) {
    #pragma unroll
    for (int k = 0; k < 16; ++k) amP[k*257 + p] = acc[k];
  }
  __syncthreads();
  if (hf == 0) {
    float mx = -3.4e38f, ss = 0.f;
    #pragma unroll
    for (int k = 0; k < 16; ++k) { acc[k] = -0.5f*(acc[k] + amP[k*257 + p]); mx = fmaxf(mx, acc[k]); }
    #pragma unroll
    for (int k = 0; k < 16; ++k) { acc[k] = __expf(acc[k]-mx); ss += acc[k]; }
    float is = 1.f/ss;
    #pragma unroll
    for (int k = 0; k < 16; ++k) {
      float v = acc[k]*is;
      sa[k*257 + p] = v;
      g_Q[(size_t)(b*1024 + blk*16 + k)*256 + p] = v;
    }
  }
  __syncthreads();
  // S[k] = sum_p sa
  { int k = t >> 5, u = t & 31;
    float sp = 0.f;
    #pragma unroll
    for (int q = 0; q < 8; ++q) sp += sa[k*257 + u + 32*q];
    red[k*33 + u] = sp; }
  __syncthreads();
  if (t < 16) { float s2 = 0.f;
    #pragma unroll
    for (int u = 0; u < 32; ++u) s2 += red[t*33+u];
    Ssm[t] = s2; }
  __syncthreads();
  // am[k][c] = sum_p sa[k][p]*pix[c][p]; warp w: 4 k's, quarter of pixels
  { int w = t >> 5, l = t & 31;
    int kg = (w & 3)*4, ph = w >> 2;
    float am[4][4];
    #pragma unroll
    for (int a1 = 0; a1 < 4; ++a1)
      #pragma unroll
      for (int a2 = 0; a2 < 4; ++a2) am[a1][a2] = 0.f;
    for (int pp = ph*64; pp < ph*64 + 64; ++pp) {
      float sv[4];
      #pragma unroll
      for (int kq = 0; kq < 4; ++kq) sv[kq] = sa[(kg+kq)*257 + pp];
      #pragma unroll
      for (int j = 0; j < 4; ++j) {
        float pv = pix[(l + 32*j)*257 + pp];
        #pragma unroll
        for (int kq = 0; kq < 4; ++kq) am[kq][j] = fmaf(sv[kq], pv, am[kq][j]);
      }
    }
    #pragma unroll
    for (int kq = 0; kq < 4; ++kq)
      #pragma unroll
      for (int j = 0; j < 4; ++j)
        amP[ph*2048 + (kg+kq)*128 + l + 32*j] = am[kq][j];
  }
  __syncthreads();
  // finalize nodes + row l2 norm -> feats
  { int k = t >> 5, u = t & 31;
    float Sv = Ssm[k], val[4], nn = 0.f;
    #pragma unroll
    for (int j = 0; j < 4; ++j) {
      int c = u + 32*j;
      float amt = amP[k*128+c] + amP[2048+k*128+c] + amP[4096+k*128+c] + amP[6144+k*128+c];
      float2 q = anc[k*128 + c];
      float v = fmaf(amt, q.x, -q.y*Sv);     // (am - a*S)*inv ; /(S+eps) & global norm cancel
      val[j] = v; nn = fmaf(v, v, nn);
    }
    red[k*33 + u] = nn;
    __syncthreads();
    if (t < 16) { float s2 = 0.f;
      #pragma unroll
      for (int u2 = 0; u2 < 32; ++u2) s2 += red[t*33+u2];
      Isn[t] = rsqrtf(fmaxf(s2, 1e-24f)); }
    __syncthreads();
    float iv = Isn[k];
    #pragma unroll
    for (int j = 0; j < 4; ++j)
      g_feats[(size_t)(b*1024 + blk*16 + k)*128 + u + 32*j] = val[j]*iv;
  }
}

// ---------- Gram: adj = F F^T. grid (16,16,2), 256 thr ----------
__global__ void __launch_bounds__(256) k_gram() {
  __shared__ float As[64*33];    // [m][k]
  __shared__ float Bs[32*68];    // [k][n] transposed
  int b = blockIdx.z, i0 = blockIdx.x*64, j0 = blockIdx.y*64;
  int t = threadIdx.x, tx = t & 15, ty = t >> 4;
  float acc[4][4];
  #pragma unroll
  for (int i = 0; i < 4; ++i)
    #pragma unroll
    for (int j = 0; j < 4; ++j) acc[i][j] = 0.f;
  const float* FA = g_feats + (size_t)b*131072 + (size_t)i0*128;
  const float* FB = g_feats + (size_t)b*131072 + (size_t)j0*128;
  for (int kc = 0; kc < 4; ++kc) {
    #pragma unroll
    for (int q = 0; q < 2; ++q) {
      int fi = t + 256*q, r = fi >> 3, k4 = fi & 7;
      float4 v = *(const float4*)&FA[(size_t)r*128 + kc*32 + k4*4];
      As[r*33 + k4*4 + 0] = v.x; As[r*33 + k4*4 + 1] = v.y;
      As[r*33 + k4*4 + 2] = v.z; As[r*33 + k4*4 + 3] = v.w;
      float4 w = *(const float4*)&FB[(size_t)r*128 + kc*32 + k4*4];
      Bs[(k4*4+0)*68 + r] = w.x; Bs[(k4*4+1)*68 + r] = w.y;
      Bs[(k4*4+2)*68 + r] = w.z; Bs[(k4*4+3)*68 + r] = w.w;
    }
    __syncthreads();
    #pragma unroll
    for (int kk = 0; kk < 32; ++kk) {
      float av[4];
      #pragma unroll
      for (int i = 0; i < 4; ++i) av[i] = As[(ty*4+i)*33 + kk];
      float4 bq = *(const float4*)&Bs[kk*68 + tx*4];
      #pragma unroll
      for (int i = 0; i < 4; ++i) {
        acc[i][0] = fmaf(av[i], bq.x, acc[i][0]);
        acc[i][1] = fmaf(av[i], bq.y, acc[i][1]);
        acc[i][2] = fmaf(av[i], bq.z, acc[i][2]);
        acc[i][3] = fmaf(av[i], bq.w, acc[i][3]);
      }
    }
    __syncthreads();
  }
  #pragma unroll
  for (int i = 0; i < 4; ++i) {
    float4 o = make_float4(acc[i][0], acc[i][1], acc[i][2], acc[i][3]);
    *(float4*)&g_adj[(size_t)b*1048576 + (size_t)(i0+ty*4+i)*1024 + j0 + tx*4] = o;
  }
}

// ---------- gates (+ pmax zero fold) ----------
__global__ void __launch_bounds__(256) k_gates(const float* __restrict__ ws,
    const float* __restrict__ wd, const float* __restrict__ bg) {
  if (blockIdx.x < 3) { int i = blockIdx.x*256 + threadIdx.x; if (i < 768) g_pmaxI[i] = 0; }
  int row = blockIdx.x*8 + (threadIdx.x >> 5), l = threadIdx.x & 31;
  float4 f = *(const float4*)&g_feats[(size_t)row*128 + l*4];
  #pragma unroll
  for (int s = 0; s < 3; ++s) {
    float4 a = *(const float4*)&ws[s*128 + l*4];
    float4 d = *(const float4*)&wd[s*128 + l*4];
    float gi = f.x*a.x + f.y*a.y + f.z*a.z + f.w*a.w;
    float gj = f.x*d.x + f.y*d.y + f.z*d.z + f.w*d.w;
    #pragma unroll
    for (int o = 16; o > 0; o >>= 1) {
      gi += __shfl_xor_sync(0xffffffffu, gi, o);
      gj += __shfl_xor_sync(0xffffffffu, gj, o);
    }
    if (l == 0) { g_egi[s*2048+row] = __expf(-(gi + bg[s])); g_egj[s*2048+row] = __expf(-gj); }
  }
}

// ---------- shared 64x64-tile mm: O_tile = A[64x128] @ W[128x128] cols [col0,col0+64) ----------
DI void mm64(const float* __restrict__ A, const float* __restrict__ W, int col0,
             float acc[4][4], float* As, float* Ws) {
  int t = threadIdx.x, tx = t & 15, ty = t >> 4;
  #pragma unroll
  for (int i = 0; i < 4; ++i)
    #pragma unroll
    for (int j = 0; j < 4; ++j) acc[i][j] = 0.f;
  for (int kc = 0; kc < 4; ++kc) {
    #pragma unroll
    for (int q = 0; q < 8; ++q) { int fi = t + 256*q, r = fi >> 5, kk = fi & 31;
      As[r*33+kk] = A[(size_t)r*128 + kc*32 + kk]; }
    #pragma unroll
    for (int q = 0; q < 4; ++q) { int fi = t + 256*q, r = fi >> 5, n2 = fi & 31;
      *(float2*)&Ws[r*68 + n2*2] = *(const float2*)&W[(size_t)(kc*32+r)*128 + col0 + n2*2]; }
    __syncthreads();
    #pragma unroll
    for (int kk = 0; kk < 32; ++kk) {
      float av[4];
      #pragma unroll
      for (int i = 0; i < 4; ++i) av[i] = As[(ty*4+i)*33 + kk];
      float4 bq = *(const float4*)&Ws[kk*68 + tx*4];
      #pragma unroll
      for (int i = 0; i < 4; ++i) {
        acc[i][0] = fmaf(av[i], bq.x, acc[i][0]);
        acc[i][1] = fmaf(av[i], bq.y, acc[i][1]);
        acc[i][2] = fmaf(av[i], bq.z, acc[i][2]);
        acc[i][3] = fmaf(av[i], bq.w, acc[i][3]);
      }
    }
    __syncthreads();
  }
}

// ---------- feats @ {W_root,W_nbr}. grid (32,2,6) ----------
__global__ void __launch_bounds__(256) k_mm6(const float* __restrict__ Wr, const float* __restrict__ Wn) {
  __shared__ float As[2112], Ws[2176];
  int z = blockIdx.z;
  const float* W = (z < 3) ? Wr + z*16384 : Wn + (z-3)*16384;
  float* O = (z < 3) ? g_froot + (size_t)z*262144 : g_fnbr + (size_t)(z-3)*262144;
  int rt = blockIdx.x*64, col0 = blockIdx.y*64;
  float acc[4][4];
  mm64(g_feats + (size_t)rt*128, W, col0, acc, As, Ws);
  int tx = threadIdx.x & 15, ty = threadIdx.x >> 4;
  #pragma unroll
  for (int i = 0; i < 4; ++i)
    *(float4*)&O[(size_t)(rt+ty*4+i)*128 + col0 + tx*4] =
      make_float4(acc[i][0], acc[i][1], acc[i][2], acc[i][3]);
}

// ---------- dense masked-gated aggregation: cout = froot + (mask*adj*gate) @ fnbr ----------
// grid (16, 2, 6): 64-row x 64-col tiles, z = s*2+b. s=0 is block-diagonal: k-band only.
__global__ void __launch_bounds__(256) k_aggd() {
  __shared__ float As[64*33];    // gated A tile [i][k]
  __shared__ float Bs[32*68];    // fnbr tile [k][c]
  int sb = blockIdx.z, s = sb >> 1, b = sb & 1;
  int i0 = blockIdx.x*64, c0 = blockIdx.y*64;
  int t = threadIdx.x, tx = t & 15, ty = t >> 4;
  float thr = (s == 0) ? 0.7f : ((s == 1) ? 0.5f : 0.3f);
  const float* adj = g_adj + (size_t)b*1048576;
  const float* egi = g_egi + s*2048 + b*1024;
  const float* egj = g_egj + s*2048 + b*1024;
  const float* FN  = g_fnbr + (size_t)s*262144 + (size_t)b*131072;
  float acc[4][4];
  #pragma unroll
  for (int i = 0; i < 4; ++i)
    #pragma unroll
    for (int j = 0; j < 4; ++j) acc[i][j] = 0.f;
  // s=0 touches only same-block columns: for the 64-aligned row tile that is k in [i0, i0+64)
  int kbeg = (s == 0) ? i0 : 0;
  int kend = (s == 0) ? i0 + 64 : 1024;
  for (int k0 = kbeg; k0 < kend; k0 += 32) {
    #pragma unroll
    for (int q = 0; q < 2; ++q) {
      int fi = t + 256*q;
      { int r = fi >> 3, k4 = fi & 7;           // A tile: 64 rows x 8 float4
        int i = i0 + r;
        float4 a4 = *(const float4*)&adj[(size_t)i*1024 + k0 + k4*4];
        float4 e4 = *(const float4*)&egj[k0 + k4*4];
        float eiv = egi[i];
        float av[4] = {a4.x, a4.y, a4.z, a4.w};
        float ev[4] = {e4.x, e4.y, e4.z, e4.w};
        int iblk = i >> 4;
        #pragma unroll
        for (int e = 0; e < 4; ++e) {
          int j = k0 + k4*4 + e;
          bool same = ((j >> 4) == iblk);
          bool ok = (av[e] > thr) && (s == 0 ? same : (s == 1 ? !same : true));
          float g = __fdividef(av[e], 1.f + eiv*ev[e]);
          As[r*33 + k4*4 + e] = ok ? g : 0.f;
        }
      }
      { int kk = fi >> 4, n4 = fi & 15;         // B tile: 32 rows x 16 float4
        *(float4*)&Bs[kk*68 + n4*4] = *(const float4*)&FN[(size_t)(k0+kk)*128 + c0 + n4*4];
      }
    }
    __syncthreads();
    #pragma unroll
    for (int kk = 0; kk < 32; ++kk) {
      float av[4];
      #pragma unroll
      for (int i = 0; i < 4; ++i) av[i] = As[(ty*4+i)*33 + kk];
      float4 bq = *(const float4*)&Bs[kk*68 + tx*4];
      #pragma unroll
      for (int i = 0; i < 4; ++i) {
        acc[i][0] = fmaf(av[i], bq.x, acc[i][0]);
        acc[i][1] = fmaf(av[i], bq.y, acc[i][1]);
        acc[i][2] = fmaf(av[i], bq.z, acc[i][2]);
        acc[i][3] = fmaf(av[i], bq.w, acc[i][3]);
      }
    }
    __syncthreads();
  }
  #pragma unroll
  for (int i = 0; i < 4; ++i) {
    size_t off = (size_t)s*262144 + (size_t)(b*1024 + i0 + ty*4 + i)*128 + c0 + tx*4;
    float4 fr = *(const float4*)&g_froot[off];
    *(float4*)&g_cout[off] =
      make_float4(acc[i][0]+fr.x, acc[i][1]+fr.y, acc[i][2]+fr.z, acc[i][3]+fr.w);
  }
}

// ---------- BN stats 2-stage ----------
__global__ void __launch_bounds__(256) k_bn1() {
  __shared__ float s1[256], s2[256];
  int blk = blockIdx.x, s = blk >> 4, seg = blk & 15;
  int c = threadIdx.x & 127, g = threadIdx.x >> 7;
  float su = 0.f, sq = 0.f;
  const float* P = g_cout + (size_t)s*262144 + (size_t)seg*16384;
  for (int r = g; r < 128; r += 2) { float v = P[(size_t)r*128 + c]; su += v; sq = fmaf(v, v, sq); }
  s1[threadIdx.x] = su; s2[threadIdx.x] = sq;
  __syncthreads();
  if (threadIdx.x < 128) {
    g_bnp[blk*128 + c] = s1[c] + s1[128+c];
    g_bnp[6144 + blk*128 + c] = s2[c] + s2[128+c];
  }
}
__global__ void __launch_bounds__(128) k_bn2() {
  int s = blockIdx.x, c = threadIdx.x;
  float su = 0.f, sq = 0.f;
  #pragma unroll
  for (int seg = 0; seg < 16; ++seg) {
    su += g_bnp[(s*16+seg)*128 + c];
    sq += g_bnp[6144 + (s*16+seg)*128 + c];
  }
  float mu = su * (1.f/2048.f);
  g_mu[s*128+c] = mu;
  g_var[s*128+c] = fmaxf(sq*(1.f/2048.f) - mu*mu, 0.f);
}

// ---------- h = bn(cout) + feats ----------
__global__ void __launch_bounds__(256) k_h(const float* __restrict__ gam, const float* __restrict__ bet) {
  int i = blockIdx.x*256 + threadIdx.x;
  int s = i >> 18, c = i & 127, si = s*128 + c, rc = i & 262143;
  float v = g_cout[i];
  g_h[i] = gam[si]*(v - g_mu[si])*rsqrtf(g_var[si] + 1e-5f) + bet[si] + g_feats[rc];
}

// ---------- att + relu + pool max. grid (32,2,3) ----------
__global__ void __launch_bounds__(256) k_att(const float* __restrict__ attW, const float* __restrict__ attb) {
  __shared__ float As[2112], Ws[2176], redm[16*68];
  int s = blockIdx.z, rt = blockIdx.x*64, col0 = blockIdx.y*64, b = rt >> 10;
  float acc[4][4];
  const float* H = g_h + (size_t)s*262144;
  mm64(H + (size_t)rt*128, attW + s*16384, col0, acc, As, Ws);
  int tx = threadIdx.x & 15, ty = threadIdx.x >> 4;
  float cm[4] = {0.f, 0.f, 0.f, 0.f};
  #pragma unroll
  for (int i = 0; i < 4; ++i) {
    int r = rt + ty*4 + i;
    #pragma unroll
    for (int j = 0; j < 4; ++j) {
      int c = col0 + tx*4 + j;
      float hv = H[(size_t)r*128 + c];
      float y = fmaxf(sigm(acc[i][j] + attb[s*128+c]) * hv, 0.f);
      g_ys[(size_t)s*262144 + (size_t)r*128 + c] = y;
      cm[j] = fmaxf(cm[j], y);
    }
  }
  #pragma unroll
  for (int j = 0; j < 4; ++j) redm[ty*68 + tx*4 + j] = cm[j];
  __syncthreads();
  int t = threadIdx.x;
  if (t < 64) {
    float m = 0.f;
    #pragma unroll
    for (int q = 0; q < 16; ++q) m = fmaxf(m, redm[q*68 + t]);
    atomicMax(&g_pmaxI[(s*2+b)*128 + col0 + t], __float_as_int(m));
  }
}

// ---------- pool MLP. grid 6 (e=s*2+b), 128 thr ----------
__global__ void __launch_bounds__(128) k_mlp(const float* __restrict__ W1, const float* __restrict__ b1,
    const float* __restrict__ W2, const float* __restrict__ b2) {
  __shared__ float p[128], h1[128];
  int e = blockIdx.x, s = e >> 1, c = threadIdx.x;
  p[c] = __int_as_float(g_pmaxI[e*128 + c]);
  __syncthreads();
  float a = b1[s*128 + c];
  for (int k = 0; k < 128; ++k) a = fmaf(p[k], W1[s*16384 + k*128 + c], a);
  h1[c] = fmaxf(a, 0.f);
  __syncthreads();
  float o = b2[s*128 + c];
  for (int k = 0; k < 128; ++k) o = fmaf(h1[k], W2[s*16384 + k*128 + c], o);
  g_pools[e*128 + c] = sigm(o);
}

// ---------- scale mixing: a, softmax, coef ----------
__global__ void __launch_bounds__(128) k_mix(const float* __restrict__ lw, const float* __restrict__ lb) {
  __shared__ float part[6][4], aa[6], Ash[6];
  int c = threadIdx.x, w = c >> 5, l = c & 31;
  for (int e = 0; e < 6; ++e) {
    int s = e >> 1;
    float v = g_pools[e*128 + c] * lw[s*128 + c];
    #pragma unroll
    for (int o = 16; o > 0; o >>= 1) v += __shfl_xor_sync(0xffffffffu, v, o);
    if (l == 0) part[e][w] = v;
  }
  __syncthreads();
  if (c < 6) aa[c] = part[c][0] + part[c][1] + part[c][2] + part[c][3] + lb[c >> 1];
  __syncthreads();
  if (c < 2) {
    float a0 = aa[0*2+c], a1 = aa[1*2+c], a2 = aa[2*2+c];
    float m = fmaxf(a0, fmaxf(a1, a2));
    float e0 = __expf(a0-m), e1 = __expf(a1-m), e2 = __expf(a2-m);
    float is = 1.f / (e0+e1+e2);
    Ash[0*2+c] = e0*is; Ash[1*2+c] = e1*is; Ash[2*2+c] = e2*is;
  }
  __syncthreads();
  for (int e = 0; e < 6; ++e) g_coef[e*128 + c] = Ash[e] * g_pools[e*128 + c];
}

// ---------- yfin = (sum_s coef*ys) @ lineFu_W + b  (fuse computed in A-load). grid (32,2) ----------
__global__ void __launch_bounds__(256) k_yfin(const float* __restrict__ W, const float* __restrict__ bias) {
  __shared__ float As[2112], Ws[2176], cf[384];
  int rt = blockIdx.x*64, col0 = blockIdx.y*64, b = rt >> 10;
  int t = threadIdx.x, tx = t & 15, ty = t >> 4;
  if (t < 128) {
    cf[t]       = g_coef[(0*2 + b)*128 + t];
    cf[128 + t] = g_coef[(1*2 + b)*128 + t];
    cf[256 + t] = g_coef[(2*2 + b)*128 + t];
  }
  __syncthreads();
  float acc[4][4];
  #pragma unroll
  for (int i = 0; i < 4; ++i)
    #pragma unroll
    for (int j = 0; j < 4; ++j) acc[i][j] = 0.f;
  for (int kc = 0; kc < 4; ++kc) {
    #pragma unroll
    for (int q = 0; q < 2; ++q) {
      int fi = t + 256*q, r = fi >> 3, k4 = fi & 7;
      size_t off = (size_t)(rt + r)*128 + kc*32 + k4*4;
      float4 y0 = *(const float4*)&g_ys[off];
      float4 y1 = *(const float4*)&g_ys[262144 + off];
      float4 y2 = *(const float4*)&g_ys[524288 + off];
      int cb = kc*32 + k4*4;
      As[r*33+k4*4+0] = cf[cb+0]*y0.x + cf[128+cb+0]*y1.x + cf[256+cb+0]*y2.x;
      As[r*33+k4*4+1] = cf[cb+1]*y0.y + cf[128+cb+1]*y1.y + cf[256+cb+1]*y2.y;
      As[r*33+k4*4+2] = cf[cb+2]*y0.z + cf[128+cb+2]*y1.z + cf[256+cb+2]*y2.z;
      As[r*33+k4*4+3] = cf[cb+3]*y0.w + cf[128+cb+3]*y1.w + cf[256+cb+3]*y2.w;
    }
    #pragma unroll
    for (int q = 0; q < 4; ++q) { int fi = t + 256*q, r = fi >> 5, n2 = fi & 31;
      *(float2*)&Ws[r*68 + n2*2] = *(const float2*)&W[(size_t)(kc*32+r)*128 + col0 + n2*2]; }
    __syncthreads();
    #pragma unroll
    for (int kk = 0; kk < 32; ++kk) {
      float av[4];
      #pragma unroll
      for (int i = 0; i < 4; ++i) av[i] = As[(ty*4+i)*33 + kk];
      float4 bq = *(const float4*)&Ws[kk*68 + tx*4];
      #pragma unroll
      for (int i = 0; i < 4; ++i) {
        acc[i][0] = fmaf(av[i], bq.x, acc[i][0]);
        acc[i][1] = fmaf(av[i], bq.y, acc[i][1]);
        acc[i][2] = fmaf(av[i], bq.z, acc[i][2]);
        acc[i][3] = fmaf(av[i], bq.w, acc[i][3]);
      }
    }
    __syncthreads();
  }
  #pragma unroll
  for (int i = 0; i < 4; ++i)
    #pragma unroll
    for (int j = 0; j < 4; ++j)
      g_yfin[(size_t)(rt+ty*4+i)*128 + col0 + tx*4 + j] = acc[i][j] + bias[col0 + tx*4 + j];
}

// ---------- reprojection + residual. grid 128, 512 thr ----------
__global__ void __launch_bounds__(512) k_reproj(const float* __restrict__ x, float* __restrict__ out) {
  __shared__ float yf[16*130];
  int b = blockIdx.x >> 6, blk = blockIdx.x & 63, by = blk >> 3, bx = blk & 7;
  int t = threadIdx.x, base = b*1024 + blk*16;
  for (int fi = t; fi < 2048; fi += 512) { int r = fi >> 7, c = fi & 127;
    yf[r*130 + c] = g_yfin[(size_t)(base+r)*128 + c]; }
  int p = t & 255, ch = t >> 8;
  float qv[16];
  #pragma unroll
  for (int k = 0; k < 16; ++k) qv[k] = g_Q[(size_t)(base+k)*256 + p];
  __syncthreads();
  int hb = p >> 4, wb = p & 15;
  size_t o0 = (size_t)b*2097152 + (size_t)(by*16+hb)*128 + bx*16 + wb;
  for (int cc = 0; cc < 64; ++cc) {
    int c = ch*64 + cc;
    float acc = 0.f;
    #pragma unroll
    for (int k = 0; k < 16; ++k) acc = fmaf(yf[k*130 + c], qv[k], acc);
    out[o0 + (size_t)c*16384] = acc + x[o0 + (size_t)c*16384];
  }
}

extern "C" void kernel_launch(void* const* d_in, const int* in_sizes, int n_in,
                              void* d_out, int out_size) {
  const float* x     = (const float*)d_in[0];
  const float* anc   = (const float*)d_in[1];
  const float* sig   = (const float*)d_in[2];
  const float* Wroot = (const float*)d_in[3];
  const float* Wnbr  = (const float*)d_in[4];
  const float* wgs   = (const float*)d_in[5];
  const float* wgd   = (const float*)d_in[6];
  const float* bgate = (const float*)d_in[7];
  const float* gam   = (const float*)d_in[8];
  const float* bet   = (const float*)d_in[9];
  const float* attW  = (const float*)d_in[10];
  const float* attb  = (const float*)d_in[11];
  const float* W1    = (const float*)d_in[12];
  const float* b1    = (const float*)d_in[13];
  const float* W2    = (const float*)d_in[14];
  const float* b2    = (const float*)d_in[15];
  const float* lAw   = (const float*)d_in[16];
  const float* lAb   = (const float*)d_in[17];
  const float* FuW   = (const float*)d_in[18];
  const float* Fub   = (const float*)d_in[19];
  float* out = (float*)d_out;

  cudaFuncSetAttribute(k_proj, cudaFuncAttributeMaxDynamicSharedMemorySize, 199424);

  k_proj<<<128, 512, 199424>>>(x, anc, sig);
  k_gram<<<dim3(16,16,2), 256>>>();
  k_gates<<<256, 256>>>(wgs, wgd, bgate);
  k_mm6<<<dim3(32,2,6), 256>>>(Wroot, Wnbr);
  k_aggd<<<dim3(16,2,6), 256>>>();
  k_bn1<<<48, 256>>>();
  k_bn2<<<3, 128>>>();
  k_h<<<3072, 256>>>(gam, bet);
  k_att<<<dim3(32,2,3), 256>>>(attW, attb);
  k_mlp<<<6, 128>>>(W1, b1, W2, b2);
  k_mix<<<1, 128>>>(lAw, lAb);
  k_yfin<<<dim3(32,2), 256>>>(FuW, Fub);
  k_reproj<<<128, 512>>>(x, out);
}